// round 1
// baseline (speedup 1.0000x reference)
#include <cuda_runtime.h>
#include <math_constants.h>

// Problem constants
#define NB 32
#define NP 576
#define ND 768
#define KP1 17
#define KF 16
#define NC 200
#define TILE_P 64
#define NTILES 9      // 576 / 64
#define T1 512

// Output layout: concatenation of (A, v_norm, logits_parts, logits_agg)
#define SZ_A (NB*KP1*NP)            // 313344
#define OFF_VN (SZ_A)               // 313344
#define SZ_VN (NB*KF*ND)            // 393216
#define OFF_PARTS (OFF_VN + SZ_VN)  // 706560
#define SZ_PARTS (NB*KF*NC)         // 102400
#define OFF_AGG (OFF_PARTS + SZ_PARTS) // 808960

// Scratch accumulator for v_all[:, :K, :] (pre-LayerNorm), zeroed each launch.
__device__ float g_v[NB*KF*ND];

// ---------------------------------------------------------------------------
// init: zero v accumulator, seed logits_parts/logits_agg with b_cls so the
// classifier kernel can use pure red.global.add.
// ---------------------------------------------------------------------------
__global__ void init_k(float* __restrict__ out, const float* __restrict__ b_cls)
{
    int i = blockIdx.x * blockDim.x + threadIdx.x;
    if (i < NB*KF*ND)  g_v[i] = 0.f;
    if (i < SZ_PARTS)  out[OFF_PARTS + i] = b_cls[i % NC];
    if (i < NB*NC)     out[OFF_AGG + i]   = b_cls[i % NC];
}

// ---------------------------------------------------------------------------
// k1: per (image, 64-patch tile) block.
//  Phase 1: dists -> softmax -> A output + a in smem  (x_sq cancels in softmax)
//  Phase 2: v[k][d] += a[p][k] * x[p][d]  accumulated in regs, one vectorized
//           red.global.add per (k, d-pair).
// ---------------------------------------------------------------------------
__global__ __launch_bounds__(T1, 1)
void k1(const float* __restrict__ x,
        const float* __restrict__ proto,
        float* __restrict__ out)
{
    extern __shared__ float sm[];
    float* xs  = sm;                      // TILE_P * ND floats (192 KB)
    float* a_s = xs + TILE_P*ND;          // TILE_P * KP1 (dist scratch then a)
    float* psq = a_s + TILE_P*KP1;        // KP1

    const int t = threadIdx.x, warp = t >> 5, lane = t & 31;
    const int b = blockIdx.y, tile = blockIdx.x;

    // --- stage x tile into smem (float4, fully coalesced) ---
    float4* xs4 = (float4*)xs;
    const float4* xg = (const float4*)(x + ((size_t)b*NP + (size_t)tile*TILE_P) * ND);
    #pragma unroll
    for (int i = 0; i < (TILE_P*ND/4)/T1; i++)   // 24 iters
        xs4[t + i*T1] = xg[t + i*T1];

    // --- ||p_k||^2: warp w handles k=w; warp 0 also k=16 ---
    {
        float s = 0.f;
        for (int i = lane; i < ND; i += 32) { float v = __ldg(&proto[warp*ND + i]); s += v*v; }
        #pragma unroll
        for (int o = 16; o; o >>= 1) s += __shfl_xor_sync(0xffffffffu, s, o);
        if (lane == 0) psq[warp] = s;
        if (warp == 0) {
            float s2 = 0.f;
            for (int i = lane; i < ND; i += 32) { float v = __ldg(&proto[16*ND + i]); s2 += v*v; }
            #pragma unroll
            for (int o = 16; o; o >>= 1) s2 += __shfl_xor_sync(0xffffffffu, s2, o);
            if (lane == 0) psq[16] = s2;
        }
    }
    __syncthreads();

    // --- Phase 1: each warp owns 4 patches; 68 dot products of length 768 ---
    const int p0 = warp * 4;
    float acc[4][KP1];
    #pragma unroll
    for (int p = 0; p < 4; p++)
        #pragma unroll
        for (int k = 0; k < KP1; k++) acc[p][k] = 0.f;

    const float4* pr4 = (const float4*)proto;
    for (int j = 0; j < 6; j++) {
        float4 xv[4];
        #pragma unroll
        for (int p = 0; p < 4; p++) xv[p] = xs4[(p0 + p)*(ND/4) + j*32 + lane];
        #pragma unroll
        for (int k = 0; k < KP1; k++) {
            float4 pv = __ldg(&pr4[k*(ND/4) + j*32 + lane]);   // L1-resident
            #pragma unroll
            for (int p = 0; p < 4; p++) {
                acc[p][k] += xv[p].x*pv.x + xv[p].y*pv.y + xv[p].z*pv.z + xv[p].w*pv.w;
            }
        }
    }

    // lane-reduce the 68 partial dots
    #pragma unroll
    for (int p = 0; p < 4; p++)
        #pragma unroll
        for (int k = 0; k < KP1; k++) {
            float v = acc[p][k];
            #pragma unroll
            for (int o = 16; o; o >>= 1) v += __shfl_xor_sync(0xffffffffu, v, o);
            acc[p][k] = v;
        }

    // park raw dots in a_s so lanes can index by k without dynamic reg indexing
    if (lane == 0) {
        #pragma unroll
        for (int p = 0; p < 4; p++)
            #pragma unroll
            for (int k = 0; k < KP1; k++) a_s[(p0 + p)*KP1 + k] = acc[p][k];
    }
    __syncwarp();

    // lane-parallel softmax: lane k owns class k (softmax(2*xp - psq) == softmax(-dists))
    #pragma unroll
    for (int p = 0; p < 4; p++) {
        const int pl = p0 + p;
        float s = (lane < KP1) ? fmaf(2.f, a_s[pl*KP1 + lane], -psq[lane]) : -CUDART_INF_F;
        float m = s;
        #pragma unroll
        for (int o = 16; o; o >>= 1) m = fmaxf(m, __shfl_xor_sync(0xffffffffu, m, o));
        float e = (lane < KP1) ? __expf(s - m) : 0.f;
        float ssum = e;
        #pragma unroll
        for (int o = 16; o; o >>= 1) ssum += __shfl_xor_sync(0xffffffffu, ssum, o);
        float av = e * (1.f / ssum);
        if (lane < KP1) {
            a_s[pl*KP1 + lane] = av;
            // A[b][k][p] layout
            out[((size_t)b*KP1 + lane)*NP + (size_t)tile*TILE_P + pl] = av;
        }
    }
    __syncthreads();

    // --- Phase 2: d-partitioned accumulation of v (k < 16 only) ---
    if (t < ND/2) {                       // 384 threads, float2 over d
        float2 vacc[KF];
        #pragma unroll
        for (int k = 0; k < KF; k++) { vacc[k].x = 0.f; vacc[k].y = 0.f; }
        const float2* xs2 = (const float2*)xs;
        for (int p = 0; p < TILE_P; p++) {
            float2 xv = xs2[p*(ND/2) + t];
            #pragma unroll
            for (int k = 0; k < KF; k++) {
                float av = a_s[p*KP1 + k];           // smem broadcast
                vacc[k].x += av * xv.x;
                vacc[k].y += av * xv.y;
            }
        }
        float2* gv = (float2*)(g_v + (size_t)b*KF*ND);
        #pragma unroll
        for (int k = 0; k < KF; k++)
            atomicAdd(&gv[k*(ND/2) + t], vacc[k]);   // red.global.add.v2.f32
    }
}

// ---------------------------------------------------------------------------
// k2a: LayerNorm over D for each (b,k). Applies the /P scaling here.
// ---------------------------------------------------------------------------
__global__ __launch_bounds__(256, 1)
void k2a(float* __restrict__ out,
         const float* __restrict__ gamma, const float* __restrict__ beta)
{
    const int bk = blockIdx.x;            // b*16 + k
    const int t = threadIdx.x;
    __shared__ float red[16];
    __shared__ float stats[2];
    const float* gv = g_v + (size_t)bk*ND;
    const float invP = 1.f / (float)NP;

    float v[3]; float s = 0.f, sq = 0.f;
    #pragma unroll
    for (int i = 0; i < 3; i++) {
        float val = gv[t + i*256] * invP;
        v[i] = val; s += val; sq += val*val;
    }
    #pragma unroll
    for (int o = 16; o; o >>= 1) {
        s  += __shfl_xor_sync(0xffffffffu, s, o);
        sq += __shfl_xor_sync(0xffffffffu, sq, o);
    }
    if ((t & 31) == 0) { red[t >> 5] = s; red[8 + (t >> 5)] = sq; }
    __syncthreads();
    if (t == 0) {
        float S = 0.f, Q = 0.f;
        #pragma unroll
        for (int w = 0; w < 8; w++) { S += red[w]; Q += red[8 + w]; }
        float mu  = S * (1.f/ND);
        float var = Q * (1.f/ND) - mu*mu;
        stats[0] = mu; stats[1] = rsqrtf(var + 1e-6f);
    }
    __syncthreads();
    const float mu = stats[0], rs = stats[1];
    #pragma unroll
    for (int i = 0; i < 3; i++) {
        int d = t + i*256;
        out[OFF_VN + (size_t)bk*ND + d] = (v[i] - mu) * rs * gamma[d] + beta[d];
    }
}

// ---------------------------------------------------------------------------
// k2b: logits_parts[b,k,c] += vn[b,k,dchunk] @ w[dchunk,c]; agg folded in.
// Bias was pre-seeded by init_k, so this is pure accumulation.
// ---------------------------------------------------------------------------
__global__ __launch_bounds__(256, 1)
void k2b(const float* __restrict__ w, float* __restrict__ out)
{
    const int dc = blockIdx.x;            // 0..3, chunk of 192 d's
    const int b  = blockIdx.y;
    const int t  = threadIdx.x;
    __shared__ float vn_s[KF*192];

    const float* vn = out + OFF_VN + (size_t)b*KF*ND + dc*192;
    for (int i = t; i < KF*192; i += 256) {
        int k = i / 192, dd = i - k*192;
        vn_s[i] = vn[(size_t)k*ND + dd];
    }
    __syncthreads();

    if (t < NC) {
        const float* wp = w + (size_t)(dc*192)*NC + t;   // w[d][c], coalesced in c
        float acc[KF];
        #pragma unroll
        for (int k = 0; k < KF; k++) acc[k] = 0.f;
        #pragma unroll 4
        for (int d = 0; d < 192; d++) {
            float wv = __ldg(wp + (size_t)d*NC);
            #pragma unroll
            for (int k = 0; k < KF; k++) acc[k] += vn_s[k*192 + d] * wv;
        }
        float* parts = out + OFF_PARTS + (size_t)b*KF*NC + t;
        float ssum = 0.f;
        #pragma unroll
        for (int k = 0; k < KF; k++) { atomicAdd(parts + (size_t)k*NC, acc[k]); ssum += acc[k]; }
        atomicAdd(out + OFF_AGG + b*NC + t, ssum * (1.f/KF));
    }
}

// ---------------------------------------------------------------------------
extern "C" void kernel_launch(void* const* d_in, const int* in_sizes, int n_in,
                              void* d_out, int out_size)
{
    const float* x     = (const float*)d_in[0];  // (32,24,24,768)
    const float* proto = (const float*)d_in[1];  // (17,768)
    const float* gamma = (const float*)d_in[2];  // (768,)
    const float* beta  = (const float*)d_in[3];  // (768,)
    const float* w     = (const float*)d_in[4];  // (768,200)
    const float* bc    = (const float*)d_in[5];  // (200,)
    float* out = (float*)d_out;

    const size_t smem1 = (size_t)(TILE_P*ND + TILE_P*KP1 + KP1) * sizeof(float); // ~201 KB
    cudaFuncSetAttribute(k1, cudaFuncAttributeMaxDynamicSharedMemorySize, (int)smem1);

    init_k<<<(NB*KF*ND + 255)/256, 256>>>(out, bc);
    k1<<<dim3(NTILES, NB), T1, smem1>>>(x, proto, out);
    k2a<<<NB*KF, 256>>>(out, gamma, beta);
    k2b<<<dim3(4, NB), 256>>>(w, out);
}

// round 3
// speedup vs baseline: 1.1226x; 1.1226x over previous
#include <cuda_runtime.h>
#include <math_constants.h>

// Problem constants
#define NB 32
#define NP 576
#define ND 768
#define KP1 17
#define KF 16
#define NC 200
#define TILE_P 32
#define NTILES 18     // 576 / 32
#define T1 256
#define NDV 192       // ulonglong2 (4 floats) per 768-float row

// Output layout: concatenation of (A, v_norm, logits_parts, logits_agg)
#define SZ_A (NB*KP1*NP)            // 313344
#define OFF_VN (SZ_A)
#define SZ_VN (NB*KF*ND)            // 393216
#define OFF_PARTS (OFF_VN + SZ_VN)
#define SZ_PARTS (NB*KF*NC)         // 102400
#define OFF_AGG (OFF_PARTS + SZ_PARTS)

typedef unsigned long long u64;

__device__ float g_v[NB*KF*ND];     // v accumulator (pre-LN), zeroed per launch
__device__ float g_psq[KP1];        // ||p_k||^2

// ---- f32x2 packed-FMA helpers ----------------------------------------------
__device__ __forceinline__ u64 fma2(u64 a, u64 b, u64 c) {
    u64 d; asm("fma.rn.f32x2 %0, %1, %2, %3;" : "=l"(d) : "l"(a), "l"(b), "l"(c));
    return d;
}
__device__ __forceinline__ u64 pack2(float lo, float hi) {
    u64 r; asm("mov.b64 %0, {%1,%2};" : "=l"(r) : "f"(lo), "f"(hi));
    return r;
}
__device__ __forceinline__ float2 unpack2(u64 v) {
    float2 r; asm("mov.b64 {%0,%1}, %2;" : "=f"(r.x), "=f"(r.y) : "l"(v));
    return r;
}

// ---------------------------------------------------------------------------
// init: zero v accumulator, seed logits_parts/logits_agg with b_cls, and
// compute ||p_k||^2 once (block 0).
// ---------------------------------------------------------------------------
__global__ void init_k(float* __restrict__ out, const float* __restrict__ b_cls,
                       const float* __restrict__ proto)
{
    int i = blockIdx.x * blockDim.x + threadIdx.x;
    if (i < SZ_VN)    g_v[i] = 0.f;
    if (i < SZ_PARTS) out[OFF_PARTS + i] = b_cls[i % NC];
    if (i < NB*NC)    out[OFF_AGG + i]   = b_cls[i % NC];

    if (blockIdx.x == 0) {
        int warp = threadIdx.x >> 5, lane = threadIdx.x & 31;
        for (int k = warp; k < KP1; k += 8) {
            float s = 0.f;
            for (int d = lane; d < ND; d += 32) {
                float v = __ldg(&proto[k*ND + d]); s += v*v;
            }
            #pragma unroll
            for (int o = 16; o; o >>= 1) s += __shfl_xor_sync(0xffffffffu, s, o);
            if (lane == 0) g_psq[k] = s;
        }
    }
}

// ---------------------------------------------------------------------------
// k1 phase-1 helper: packed dot products for prototypes [K0, K0+KN).
// Each warp owns 4 patches; accumulators are f32x2-packed over d.
// ---------------------------------------------------------------------------
template<int K0, int KN>
__device__ __forceinline__ void dot_pass(const ulonglong2* __restrict__ xs2,
                                         const float* __restrict__ proto,
                                         float* a_s, int warp, int lane)
{
    const int p0 = warp * 4;
    u64 acc[4][KN];
    #pragma unroll
    for (int p = 0; p < 4; p++)
        #pragma unroll
        for (int k = 0; k < KN; k++) acc[p][k] = 0ULL;

    const ulonglong2* pr2 = (const ulonglong2*)proto;
    #pragma unroll
    for (int j = 0; j < 6; j++) {
        ulonglong2 xv[4];
        #pragma unroll
        for (int p = 0; p < 4; p++) xv[p] = xs2[(p0 + p)*NDV + j*32 + lane];
        #pragma unroll
        for (int k = 0; k < KN; k++) {
            ulonglong2 pv = __ldg(&pr2[(K0 + k)*NDV + j*32 + lane]);
            #pragma unroll
            for (int p = 0; p < 4; p++) {
                acc[p][k] = fma2(xv[p].x, pv.x, acc[p][k]);
                acc[p][k] = fma2(xv[p].y, pv.y, acc[p][k]);
            }
        }
    }
    #pragma unroll
    for (int p = 0; p < 4; p++)
        #pragma unroll
        for (int k = 0; k < KN; k++) {
            float2 h = unpack2(acc[p][k]);
            float v = h.x + h.y;
            #pragma unroll
            for (int o = 16; o; o >>= 1) v += __shfl_xor_sync(0xffffffffu, v, o);
            if (lane == 0) a_s[(p0 + p)*KP1 + K0 + k] = v;
        }
}

// ---------------------------------------------------------------------------
// k1: per (image, 32-patch tile) block. 256 threads, 2 blocks/SM.
//  Phase 1: packed dots -> softmax -> A + packed a in smem
//  Phase 2: v[k][d] += a[p][k]*x[p][d], f32x2, one red.global.v4 per (k,d4)
// ---------------------------------------------------------------------------
__global__ __launch_bounds__(T1, 2)
void k1(const float* __restrict__ x,
        const float* __restrict__ proto,
        float* __restrict__ out)
{
    extern __shared__ float sm[];
    float* xs   = sm;                              // TILE_P*ND floats (96 KB)
    float* a_s  = xs + TILE_P*ND;                  // TILE_P*KP1
    u64*   a_pk = (u64*)(a_s + TILE_P*KP1);        // TILE_P*KF packed (a,a)

    const int t = threadIdx.x, warp = t >> 5, lane = t & 31;
    const int b = blockIdx.y, tile = blockIdx.x;

    // --- stage x tile (float4, coalesced) ---
    float4* xs4 = (float4*)xs;
    const float4* xg = (const float4*)(x + ((size_t)b*NP + (size_t)tile*TILE_P)*ND);
    #pragma unroll
    for (int i = 0; i < (TILE_P*ND/4)/T1; i++)     // 24 iters
        xs4[t + i*T1] = xg[t + i*T1];
    __syncthreads();

    // --- Phase 1: dots, k-split to bound register pressure ---
    const ulonglong2* xs2 = (const ulonglong2*)xs;
    dot_pass<0, 6>(xs2, proto, a_s, warp, lane);
    dot_pass<6, 6>(xs2, proto, a_s, warp, lane);
    dot_pass<12, 5>(xs2, proto, a_s, warp, lane);
    __syncwarp();

    // --- lane-parallel softmax: softmax_k(2*xp - psq) == softmax(-dists) ---
    const int p0 = warp * 4;
    #pragma unroll
    for (int p = 0; p < 4; p++) {
        const int pl = p0 + p;
        float s = (lane < KP1) ? fmaf(2.f, a_s[pl*KP1 + lane], -g_psq[lane])
                               : -CUDART_INF_F;
        float m = s;
        #pragma unroll
        for (int o = 16; o; o >>= 1) m = fmaxf(m, __shfl_xor_sync(0xffffffffu, m, o));
        float e = (lane < KP1) ? __expf(s - m) : 0.f;
        float ssum = e;
        #pragma unroll
        for (int o = 16; o; o >>= 1) ssum += __shfl_xor_sync(0xffffffffu, ssum, o);
        float av = e * (1.f / ssum);
        if (lane < KP1) {
            a_s[pl*KP1 + lane] = av;
            if (lane < KF) a_pk[pl*KF + lane] = pack2(av, av);
        }
    }
    __syncthreads();

    if (t >= 192) {
        // --- A output, coalesced 128B rows, on otherwise-idle threads ---
        int tt = t - 192;
        #pragma unroll
        for (int i = tt; i < KP1*TILE_P; i += 64) {
            int k = i >> 5, p = i & 31;
            out[((size_t)b*KP1 + k)*NP + (size_t)tile*TILE_P + p] = a_s[p*KP1 + k];
        }
    } else {
        // --- Phase 2: 192 threads each own a d-quad (16B) ---
        ulonglong2 vacc[KF];
        #pragma unroll
        for (int k = 0; k < KF; k++) { vacc[k].x = 0ULL; vacc[k].y = 0ULL; }
        #pragma unroll 4
        for (int p = 0; p < TILE_P; p++) {
            ulonglong2 xv = xs2[p*NDV + t];
            #pragma unroll
            for (int k = 0; k < KF; k++) {
                u64 ap = a_pk[p*KF + k];               // broadcast LDS.64
                vacc[k].x = fma2(ap, xv.x, vacc[k].x);
                vacc[k].y = fma2(ap, xv.y, vacc[k].y);
            }
        }
        float4* gv4 = (float4*)(g_v + (size_t)b*KF*ND);
        #pragma unroll
        for (int k = 0; k < KF; k++) {
            float2 lo = unpack2(vacc[k].x), hi = unpack2(vacc[k].y);
            atomicAdd(&gv4[k*(ND/4) + t], make_float4(lo.x, lo.y, hi.x, hi.y));
        }
    }
}

// ---------------------------------------------------------------------------
// k2a: LayerNorm over D for each (b,k). Applies the /P scaling here.
// ---------------------------------------------------------------------------
__global__ __launch_bounds__(256, 1)
void k2a(float* __restrict__ out,
         const float* __restrict__ gamma, const float* __restrict__ beta)
{
    const int bk = blockIdx.x;            // b*16 + k
    const int t = threadIdx.x;
    __shared__ float red[16];
    __shared__ float stats[2];
    const float* gv = g_v + (size_t)bk*ND;
    const float invP = 1.f / (float)NP;

    float v[3]; float s = 0.f, sq = 0.f;
    #pragma unroll
    for (int i = 0; i < 3; i++) {
        float val = gv[t + i*256] * invP;
        v[i] = val; s += val; sq += val*val;
    }
    #pragma unroll
    for (int o = 16; o; o >>= 1) {
        s  += __shfl_xor_sync(0xffffffffu, s, o);
        sq += __shfl_xor_sync(0xffffffffu, sq, o);
    }
    if ((t & 31) == 0) { red[t >> 5] = s; red[8 + (t >> 5)] = sq; }
    __syncthreads();
    if (t == 0) {
        float S = 0.f, Q = 0.f;
        #pragma unroll
        for (int w = 0; w < 8; w++) { S += red[w]; Q += red[8 + w]; }
        float mu  = S * (1.f/ND);
        float var = Q * (1.f/ND) - mu*mu;
        stats[0] = mu; stats[1] = rsqrtf(var + 1e-6f);
    }
    __syncthreads();
    const float mu = stats[0], rs = stats[1];
    #pragma unroll
    for (int i = 0; i < 3; i++) {
        int d = t + i*256;
        out[OFF_VN + (size_t)bk*ND + d] = (v[i] - mu) * rs * gamma[d] + beta[d];
    }
}

// ---------------------------------------------------------------------------
// k2b: logits_parts[b,k,c] += vn[b,k,dchunk] @ w[dchunk,c]; agg folded in.
// 8 d-chunks of 96 per image -> 256 blocks; f32x2 over d-pairs.
// Bias pre-seeded by init_k, so pure red.global.add.
// ---------------------------------------------------------------------------
#define DCH 96
__global__ __launch_bounds__(256, 4)
void k2b(const float* __restrict__ w, float* __restrict__ out)
{
    const int dc = blockIdx.x;            // 0..7
    const int b  = blockIdx.y;
    const int t  = threadIdx.x;
    __shared__ u64 vn_s[KF*(DCH/2)];      // packed d-pairs

    const float* vn = out + OFF_VN + (size_t)b*KF*ND + dc*DCH;
    for (int i = t; i < KF*(DCH/2); i += 256) {
        int k = i / (DCH/2), dp = i - k*(DCH/2);
        float2 v = *(const float2*)&vn[(size_t)k*ND + 2*dp];
        vn_s[i] = pack2(v.x, v.y);
    }
    __syncthreads();

    if (t < NC) {
        const float* wp = w + (size_t)(dc*DCH)*NC + t;   // coalesced in c
        u64 acc[KF];
        #pragma unroll
        for (int k = 0; k < KF; k++) acc[k] = 0ULL;
        #pragma unroll 4
        for (int dp = 0; dp < DCH/2; dp++) {
            float w0 = __ldg(wp + (size_t)(2*dp)*NC);
            float w1 = __ldg(wp + (size_t)(2*dp + 1)*NC);
            u64 wv = pack2(w0, w1);
            #pragma unroll
            for (int k = 0; k < KF; k++)
                acc[k] = fma2(vn_s[k*(DCH/2) + dp], wv, acc[k]);
        }
        float* parts = out + OFF_PARTS + (size_t)b*KF*NC + t;
        float ssum = 0.f;
        #pragma unroll
        for (int k = 0; k < KF; k++) {
            float2 h = unpack2(acc[k]);
            float s = h.x + h.y;
            atomicAdd(parts + (size_t)k*NC, s);
            ssum += s;
        }
        atomicAdd(out + OFF_AGG + b*NC + t, ssum * (1.f/KF));
    }
}

// ---------------------------------------------------------------------------
extern "C" void kernel_launch(void* const* d_in, const int* in_sizes, int n_in,
                              void* d_out, int out_size)
{
    const float* x     = (const float*)d_in[0];  // (32,24,24,768)
    const float* proto = (const float*)d_in[1];  // (17,768)
    const float* gamma = (const float*)d_in[2];  // (768,)
    const float* beta  = (const float*)d_in[3];  // (768,)
    const float* w     = (const float*)d_in[4];  // (768,200)
    const float* bc    = (const float*)d_in[5];  // (200,)
    float* out = (float*)d_out;

    const size_t smem1 = (size_t)(TILE_P*ND + TILE_P*KP1) * sizeof(float)
                       + (size_t)TILE_P*KF * sizeof(u64);   // ~104.5 KB
    cudaFuncSetAttribute(k1, cudaFuncAttributeMaxDynamicSharedMemorySize, (int)smem1);

    init_k<<<(SZ_VN + 255)/256, 256>>>(out, bc, proto);
    k1<<<dim3(NTILES, NB), T1, smem1>>>(x, proto, out);
    k2a<<<NB*KF, 256>>>(out, gamma, beta);
    k2b<<<dim3(8, NB), 256>>>(w, out);
}

// round 4
// speedup vs baseline: 1.1681x; 1.0406x over previous
#include <cuda_runtime.h>
#include <math_constants.h>

// Problem constants
#define NB 32
#define NP 576
#define ND 768
#define KP1 17
#define KF 16
#define NC 200
#define TILE_P 32
#define NTILES 18     // 576 / 32
#define T1 256
#define NDV 192       // ulonglong2 (4 floats) per 768-float row

// Output layout: concatenation of (A, v_norm, logits_parts, logits_agg)
#define SZ_A (NB*KP1*NP)            // 313344
#define OFF_VN (SZ_A)
#define SZ_VN (NB*KF*ND)            // 393216
#define OFF_PARTS (OFF_VN + SZ_VN)
#define SZ_PARTS (NB*KF*NC)         // 102400
#define OFF_AGG (OFF_PARTS + SZ_PARTS)

typedef unsigned long long u64;

// v accumulator (pre-LN). Zeroed at module load; k2a re-zeroes after reading,
// so the "g_v == 0 on k1 entry" invariant holds across graph replays.
__device__ float g_v[NB*KF*ND];

// ---- f32x2 packed-FMA helpers ----------------------------------------------
__device__ __forceinline__ u64 fma2(u64 a, u64 b, u64 c) {
    u64 d; asm("fma.rn.f32x2 %0, %1, %2, %3;" : "=l"(d) : "l"(a), "l"(b), "l"(c));
    return d;
}
__device__ __forceinline__ u64 pack2(float lo, float hi) {
    u64 r; asm("mov.b64 %0, {%1,%2};" : "=l"(r) : "f"(lo), "f"(hi));
    return r;
}
__device__ __forceinline__ float2 unpack2(u64 v) {
    float2 r; asm("mov.b64 {%0,%1}, %2;" : "=f"(r.x), "=f"(r.y) : "l"(v));
    return r;
}

// ---------------------------------------------------------------------------
// k1 phase-1 helper: packed dot products for prototypes [K0, K0+KN).
// Each warp owns 4 patches; accumulators are f32x2-packed over d.
// ---------------------------------------------------------------------------
template<int K0, int KN>
__device__ __forceinline__ void dot_pass(const ulonglong2* __restrict__ xs2,
                                         const float* __restrict__ proto,
                                         float* a_s, int warp, int lane)
{
    const int p0 = warp * 4;
    u64 acc[4][KN];
    #pragma unroll
    for (int p = 0; p < 4; p++)
        #pragma unroll
        for (int k = 0; k < KN; k++) acc[p][k] = 0ULL;

    const ulonglong2* pr2 = (const ulonglong2*)proto;
    #pragma unroll
    for (int j = 0; j < 6; j++) {
        ulonglong2 xv[4];
        #pragma unroll
        for (int p = 0; p < 4; p++) xv[p] = xs2[(p0 + p)*NDV + j*32 + lane];
        #pragma unroll
        for (int k = 0; k < KN; k++) {
            ulonglong2 pv = __ldg(&pr2[(K0 + k)*NDV + j*32 + lane]);
            #pragma unroll
            for (int p = 0; p < 4; p++) {
                acc[p][k] = fma2(xv[p].x, pv.x, acc[p][k]);
                acc[p][k] = fma2(xv[p].y, pv.y, acc[p][k]);
            }
        }
    }
    #pragma unroll
    for (int p = 0; p < 4; p++)
        #pragma unroll
        for (int k = 0; k < KN; k++) {
            float2 h = unpack2(acc[p][k]);
            float v = h.x + h.y;
            #pragma unroll
            for (int o = 16; o; o >>= 1) v += __shfl_xor_sync(0xffffffffu, v, o);
            if (lane == 0) a_s[(p0 + p)*KP1 + K0 + k] = v;
        }
}

// ---------------------------------------------------------------------------
// k1: per (image, 32-patch tile) block. 256 threads, 2 blocks/SM.
//  Stage x + per-block psq -> packed dots -> softmax -> A out, packed a smem
//  Phase 2: v[k][d] += a[p][k]*x[p][d], f32x2, one red.global.v4 per (k,d4)
// ---------------------------------------------------------------------------
__global__ __launch_bounds__(T1, 2)
void k1(const float* __restrict__ x,
        const float* __restrict__ proto,
        float* __restrict__ out)
{
    extern __shared__ float sm[];
    float* xs    = sm;                             // TILE_P*ND floats (96 KB)
    float* a_s   = xs + TILE_P*ND;                 // TILE_P*KP1
    u64*   a_pk  = (u64*)(a_s + TILE_P*KP1);       // TILE_P*KF packed (a,a)
    float* psq_s = (float*)(a_pk + TILE_P*KF);     // KP1

    const int t = threadIdx.x, warp = t >> 5, lane = t & 31;
    const int b = blockIdx.y, tile = blockIdx.x;

    // --- stage x tile (float4, coalesced) ---
    float4* xs4 = (float4*)xs;
    const float4* xg = (const float4*)(x + ((size_t)b*NP + (size_t)tile*TILE_P)*ND);
    #pragma unroll
    for (int i = 0; i < (TILE_P*ND/4)/T1; i++)     // 24 iters
        xs4[t + i*T1] = xg[t + i*T1];

    // --- per-block ||p_k||^2 (proto L2-resident, overlaps the staging) ---
    for (int k = warp; k < KP1; k += 8) {          // warp0: 0,8,16
        const float4* pk = (const float4*)(proto + (size_t)k*ND);
        float s = 0.f;
        #pragma unroll
        for (int i = 0; i < 6; i++) {
            float4 v = __ldg(&pk[lane + 32*i]);
            s += v.x*v.x + v.y*v.y + v.z*v.z + v.w*v.w;
        }
        #pragma unroll
        for (int o = 16; o; o >>= 1) s += __shfl_xor_sync(0xffffffffu, s, o);
        if (lane == 0) psq_s[k] = s;
    }
    __syncthreads();

    // --- Phase 1: dots, k-split to bound register pressure ---
    const ulonglong2* xs2 = (const ulonglong2*)xs;
    dot_pass<0, 6>(xs2, proto, a_s, warp, lane);
    dot_pass<6, 6>(xs2, proto, a_s, warp, lane);
    dot_pass<12, 5>(xs2, proto, a_s, warp, lane);
    __syncwarp();

    // --- lane-parallel softmax: softmax_k(2*xp - psq) == softmax(-dists) ---
    const int p0 = warp * 4;
    #pragma unroll
    for (int p = 0; p < 4; p++) {
        const int pl = p0 + p;
        float s = (lane < KP1) ? fmaf(2.f, a_s[pl*KP1 + lane], -psq_s[lane])
                               : -CUDART_INF_F;
        float m = s;
        #pragma unroll
        for (int o = 16; o; o >>= 1) m = fmaxf(m, __shfl_xor_sync(0xffffffffu, m, o));
        float e = (lane < KP1) ? __expf(s - m) : 0.f;
        float ssum = e;
        #pragma unroll
        for (int o = 16; o; o >>= 1) ssum += __shfl_xor_sync(0xffffffffu, ssum, o);
        float av = e * (1.f / ssum);
        if (lane < KP1) {
            a_s[pl*KP1 + lane] = av;
            if (lane < KF) a_pk[pl*KF + lane] = pack2(av, av);
        }
    }
    __syncthreads();

    if (t >= 192) {
        // --- A output, coalesced 128B rows, on otherwise-idle threads ---
        int tt = t - 192;
        #pragma unroll
        for (int i = tt; i < KP1*TILE_P; i += 64) {
            int k = i >> 5, p = i & 31;
            out[((size_t)b*KP1 + k)*NP + (size_t)tile*TILE_P + p] = a_s[p*KP1 + k];
        }
    } else {
        // --- Phase 2: 192 threads each own a d-quad (16B) ---
        ulonglong2 vacc[KF];
        #pragma unroll
        for (int k = 0; k < KF; k++) { vacc[k].x = 0ULL; vacc[k].y = 0ULL; }
        #pragma unroll 4
        for (int p = 0; p < TILE_P; p++) {
            ulonglong2 xv = xs2[p*NDV + t];
            #pragma unroll
            for (int k = 0; k < KF; k++) {
                u64 ap = a_pk[p*KF + k];               // broadcast LDS.64
                vacc[k].x = fma2(ap, xv.x, vacc[k].x);
                vacc[k].y = fma2(ap, xv.y, vacc[k].y);
            }
        }
        float4* gv4 = (float4*)(g_v + (size_t)b*KF*ND);
        #pragma unroll
        for (int k = 0; k < KF; k++) {
            float2 lo = unpack2(vacc[k].x), hi = unpack2(vacc[k].y);
            atomicAdd(&gv4[k*(ND/4) + t], make_float4(lo.x, lo.y, hi.x, hi.y));
        }
    }
}

// ---------------------------------------------------------------------------
// k2a: LayerNorm over D for each (b,k). Applies the /P scaling.
// Also: re-zeroes g_v (read-then-clear) and seeds parts/agg with the bias so
// k2b can use pure atomics and no init kernel is needed.
// ---------------------------------------------------------------------------
__global__ __launch_bounds__(256, 4)
void k2a(float* __restrict__ out,
         const float* __restrict__ gamma, const float* __restrict__ beta,
         const float* __restrict__ b_cls)
{
    const int bk = blockIdx.x;            // b*16 + k
    const int t = threadIdx.x;
    __shared__ float red[16];
    __shared__ float stats[2];
    float* gv = g_v + (size_t)bk*ND;
    const float invP = 1.f / (float)NP;

    float v[3]; float s = 0.f, sq = 0.f;
    #pragma unroll
    for (int i = 0; i < 3; i++) {
        float val = gv[t + i*256] * invP;
        gv[t + i*256] = 0.f;              // re-zero for next replay's k1
        v[i] = val; s += val; sq += val*val;
    }

    // seed logits_parts / logits_agg with the classifier bias
    if (t < NC) {
        float bcv = b_cls[t];
        out[OFF_PARTS + (size_t)bk*NC + t] = bcv;
        if ((bk & 15) == 0) out[OFF_AGG + (size_t)(bk >> 4)*NC + t] = bcv;
    }

    #pragma unroll
    for (int o = 16; o; o >>= 1) {
        s  += __shfl_xor_sync(0xffffffffu, s, o);
        sq += __shfl_xor_sync(0xffffffffu, sq, o);
    }
    if ((t & 31) == 0) { red[t >> 5] = s; red[8 + (t >> 5)] = sq; }
    __syncthreads();
    if (t == 0) {
        float S = 0.f, Q = 0.f;
        #pragma unroll
        for (int w = 0; w < 8; w++) { S += red[w]; Q += red[8 + w]; }
        float mu  = S * (1.f/ND);
        float var = Q * (1.f/ND) - mu*mu;
        stats[0] = mu; stats[1] = rsqrtf(var + 1e-6f);
    }
    __syncthreads();
    const float mu = stats[0], rs = stats[1];
    #pragma unroll
    for (int i = 0; i < 3; i++) {
        int d = t + i*256;
        out[OFF_VN + (size_t)bk*ND + d] = (v[i] - mu) * rs * gamma[d] + beta[d];
    }
}

// ---------------------------------------------------------------------------
// k2b: logits_parts[b,k,c] += vn[b,k,dchunk] @ w[dchunk,c]; agg folded in.
// 16 d-chunks of 48 per image -> 512 blocks; unroll-8 for MLP; w L2-resident.
// Bias pre-seeded by k2a, so pure red.global.add.
// ---------------------------------------------------------------------------
#define DCH 48
__global__ __launch_bounds__(256, 4)
void k2b(const float* __restrict__ w, float* __restrict__ out)
{
    const int dc = blockIdx.x;            // 0..15
    const int b  = blockIdx.y;
    const int t  = threadIdx.x;
    __shared__ u64 vn_s[KF*(DCH/2)];      // packed d-pairs (3 KB)

    const float* vn = out + OFF_VN + (size_t)b*KF*ND + dc*DCH;
    for (int i = t; i < KF*(DCH/2); i += 256) {
        int k = i / (DCH/2), dp = i - k*(DCH/2);
        float2 v = *(const float2*)&vn[(size_t)k*ND + 2*dp];
        vn_s[i] = pack2(v.x, v.y);
    }
    __syncthreads();

    if (t < NC) {
        const float* wp = w + (size_t)(dc*DCH)*NC + t;   // coalesced in c
        u64 acc[KF];
        #pragma unroll
        for (int k = 0; k < KF; k++) acc[k] = 0ULL;
        #pragma unroll 8
        for (int dp = 0; dp < DCH/2; dp++) {
            float w0 = __ldg(wp + (size_t)(2*dp)*NC);
            float w1 = __ldg(wp + (size_t)(2*dp + 1)*NC);
            u64 wv = pack2(w0, w1);
            #pragma unroll
            for (int k = 0; k < KF; k++)
                acc[k] = fma2(vn_s[k*(DCH/2) + dp], wv, acc[k]);
        }
        float* parts = out + OFF_PARTS + (size_t)b*KF*NC + t;
        float ssum = 0.f;
        #pragma unroll
        for (int k = 0; k < KF; k++) {
            float2 h = unpack2(acc[k]);
            float s = h.x + h.y;
            atomicAdd(parts + (size_t)k*NC, s);
            ssum += s;
        }
        atomicAdd(out + OFF_AGG + b*NC + t, ssum * (1.f/KF));
    }
}

// ---------------------------------------------------------------------------
extern "C" void kernel_launch(void* const* d_in, const int* in_sizes, int n_in,
                              void* d_out, int out_size)
{
    const float* x     = (const float*)d_in[0];  // (32,24,24,768)
    const float* proto = (const float*)d_in[1];  // (17,768)
    const float* gamma = (const float*)d_in[2];  // (768,)
    const float* beta  = (const float*)d_in[3];  // (768,)
    const float* w     = (const float*)d_in[4];  // (768,200)
    const float* bc    = (const float*)d_in[5];  // (200,)
    float* out = (float*)d_out;

    const size_t smem1 = (size_t)(TILE_P*ND + TILE_P*KP1 + KP1) * sizeof(float)
                       + (size_t)TILE_P*KF * sizeof(u64);   // ~104.6 KB
    cudaFuncSetAttribute(k1, cudaFuncAttributeMaxDynamicSharedMemorySize, (int)smem1);

    k1<<<dim3(NTILES, NB), T1, smem1>>>(x, proto, out);
    k2a<<<NB*KF, 256>>>(out, gamma, beta, bc);
    k2b<<<dim3(16, NB), 256>>>(w, out);
}